// round 16
// baseline (speedup 1.0000x reference)
#include <cuda_runtime.h>
#include <cuda_bf16.h>
#include <stdint.h>
#include <math.h>

#define NN 150000
#define EE 2400000
#define BBG 50000
#define HF 128
#define HF2 64

#define WOFF1  0
#define WOFF2  8192
#define WOFF3  16384
#define WOFFC1 20480
#define WOFFC2 32768
#define WPAIRS 36864

#define COFF   4800000   // classifier intermediate offset in aH (words)
#define XT     4800000   // x-split tasks (NN*HF/4)
#define SCB    147       // scan blocks: ceil(150000/1024)

// ---------------- scratch (static device globals; no allocation) -------------
__device__ uint32_t g_bufH[(size_t)NN * HF / 2];      // bf162 GEMM outputs (agg input)
__device__ uint32_t g_aH[(size_t)NN * HF / 2];        // bf162 activations (GEMM input)
__device__ uint32_t g_wh[WPAIRS];                     // bf162 weights, n-major [n][k/2]
__device__ float g_dinv[NN];
__device__ int2  g_edge[EE];                          // {src, dinv[src]-as-int}
__device__ int   g_deg[NN];
__device__ int   g_rowptr[NN + 1];
__device__ int   g_cursor[NN];
__device__ int   g_part[256];

// ---------------- helpers ----------------------------------------------------
__device__ __forceinline__ uint32_t cvt2(float x, float y) {
    __nv_bfloat162 h = __floats2bfloat162_rn(x, y);
    return reinterpret_cast<uint32_t&>(h);
}

__device__ __forceinline__ void mma16816(float c[4], const uint32_t a[4], const uint32_t b[2]) {
    asm volatile(
        "mma.sync.aligned.m16n8k16.row.col.f32.bf16.bf16.f32 "
        "{%0,%1,%2,%3}, {%4,%5,%6,%7}, {%8,%9}, {%0,%1,%2,%3};"
        : "+f"(c[0]), "+f"(c[1]), "+f"(c[2]), "+f"(c[3])
        : "r"(a[0]), "r"(a[1]), "r"(a[2]), "r"(a[3]), "r"(b[0]), "r"(b[1]));
}

__device__ __forceinline__ void ldsm4(uint32_t r[4], uint32_t saddr) {
    asm volatile(
        "ldmatrix.sync.aligned.m8n8.x4.shared.b16 {%0,%1,%2,%3}, [%4];"
        : "=r"(r[0]), "=r"(r[1]), "=r"(r[2]), "=r"(r[3]) : "r"(saddr));
}

__device__ __forceinline__ void cpasync16(uint32_t smem, const void* gptr) {
    asm volatile("cp.async.cg.shared.global [%0], [%1], 16;" :: "r"(smem), "l"(gptr));
}
__device__ __forceinline__ void cp_commit() {
    asm volatile("cp.async.commit_group;");
}
template <int Nw>
__device__ __forceinline__ void cp_wait() {
    asm volatile("cp.async.wait_group %0;" :: "n"(Nw));
}

// ---------------- setup kernels ---------------------------------------------
// 4 edges per thread, vectorized dst load
__global__ void k_count(const int* __restrict__ ei) {
    int t = blockIdx.x * blockDim.x + threadIdx.x;
    if (t < EE / 4) {
        int4 d = ((const int4*)(ei + EE))[t];
        atomicAdd(&g_deg[d.x], 1);
        atomicAdd(&g_deg[d.y], 1);
        atomicAdd(&g_deg[d.z], 1);
        atomicAdd(&g_deg[d.w], 1);
    }
}

__global__ void k_scan1() {
    __shared__ int s[1024];
    int t = threadIdx.x;
    int i = blockIdx.x * 1024 + t;
    s[t] = (i < NN) ? g_deg[i] : 0;
    __syncthreads();
    for (int off = 512; off; off >>= 1) {
        if (t < off) s[t] += s[t + off];
        __syncthreads();
    }
    if (t == 0) g_part[blockIdx.x] = s[0];
}

__global__ void k_scan2() {
    __shared__ int s[256];
    int t = threadIdx.x;
    int v = (t < SCB) ? g_part[t] : 0;
    s[t] = v;
    __syncthreads();
    for (int off = 1; off < 256; off <<= 1) {
        int u = (t >= off) ? s[t - off] : 0;
        __syncthreads();
        s[t] += u;
        __syncthreads();
    }
    if (t < SCB) g_part[t] = s[t] - v;
    if (t == 255) g_rowptr[NN] = s[255];
}

__global__ void k_scan3() {
    __shared__ int s[1024];
    int t = threadIdx.x;
    int i = blockIdx.x * 1024 + t;
    int d = (i < NN) ? g_deg[i] : 0;
    s[t] = d;
    __syncthreads();
    for (int off = 1; off < 1024; off <<= 1) {
        int u = (t >= off) ? s[t - off] : 0;
        __syncthreads();
        s[t] += u;
        __syncthreads();
    }
    if (i < NN) {
        int excl = s[t] - d + g_part[blockIdx.x];
        g_rowptr[i] = excl;
        g_cursor[i] = excl;
        g_dinv[i] = rsqrtf((float)(d + 1));
    }
}

// 2 edges per thread; store (src, dinv[src]) into dense CSR
__global__ void k_scatter(const int* __restrict__ ei) {
    int t = blockIdx.x * blockDim.x + threadIdx.x;
    if (t < EE / 2) {
        int2 s = ((const int2*)ei)[t];
        int2 d = ((const int2*)(ei + EE))[t];
        int p0 = atomicAdd(&g_cursor[d.x], 1);
        g_edge[p0] = make_int2(s.x, __float_as_int(g_dinv[s.x]));
        int p1 = atomicAdd(&g_cursor[d.y], 1);
        g_edge[p1] = make_int2(s.y, __float_as_int(g_dinv[s.y]));
    }
}

// merged conversion: x chunks first, then weight pairs (n-major [n][k/2])
__global__ void k_split(const float* __restrict__ x,
                        const float* __restrict__ W1, const float* __restrict__ W2,
                        const float* __restrict__ W3, const float* __restrict__ Wc1,
                        const float* __restrict__ Wc2) {
    int i = blockIdx.x * blockDim.x + threadIdx.x;
    if (i < XT) {
        float4 v = ((const float4*)x)[i];
        ((uint2*)g_aH)[i] = make_uint2(cvt2(v.x, v.y), cvt2(v.z, v.w));
        return;
    }
    int p = i - XT;
    if (p >= WPAIRS) return;
    const float* src;
    int off, N, Kp;
    if (p < WOFF2)       { src = W1;  off = p - WOFF1;  N = 128; Kp = 64; }
    else if (p < WOFF3)  { src = W2;  off = p - WOFF2;  N = 128; Kp = 64; }
    else if (p < WOFFC1) { src = W3;  off = p - WOFF3;  N = 64;  Kp = 64; }
    else if (p < WOFFC2) { src = Wc1; off = p - WOFFC1; N = 128; Kp = 96; }
    else                 { src = Wc2; off = p - WOFFC2; N = 64;  Kp = 64; }
    int n = off / Kp, kp = off % Kp;
    g_wh[p] = cvt2(src[(size_t)(2 * kp) * N + n], src[(size_t)(2 * kp + 1) * N + n]);
}

// ---------------- bf16 MMA GEMM, single-shot K-panel load --------------------
// OMODE: 2 = bf162 out, 3 = fused 64->2 + log_softmax (final classifier)

#define BM 128

template <int KK, int BNT, int OMODE, bool FUSE>
__global__ void __launch_bounds__(256)
k_mma(const uint32_t* __restrict__ Ah, int wOff, const float* __restrict__ bias,
      float* __restrict__ Cf, uint32_t* __restrict__ OutH,
      int M,
      const float* __restrict__ Wc3, const float* __restrict__ bc3) {
    constexpr int NT = BNT / 16;
    constexpr int Kp = KK / 2;
    constexpr int S = Kp + 4;           // (Kp+4)%32==4 -> conflict-free; 16B-aligned
    constexpr int AW = BM * S;
    constexpr int KS = Kp / 8;

    extern __shared__ uint32_t smem[];

    const int tid = threadIdx.x;
    const int wid = tid >> 5;
    const int lane = tid & 31;
    const int wm = wid & 3;
    const int wn = wid >> 2;
    const int gid = lane >> 2;
    const int tig = lane & 3;
    const int bm = blockIdx.y * BM;

    const uint32_t smB = (uint32_t)__cvta_generic_to_shared(smem);
    const uint32_t sBhB = smB + AW * 4u;

    float c[2][NT][4];
#pragma unroll
    for (int mt = 0; mt < 2; mt++)
#pragma unroll
        for (int nt = 0; nt < NT; nt++)
#pragma unroll
            for (int j = 0; j < 4; j++) c[mt][nt][j] = 0.f;

    const int aRow = lane & 15;
    const int aKh = (lane >> 4) * 4;
    const int bN = (lane >> 4) * 8 + (lane & 7);
    const int bKh = ((lane >> 3) & 1) * 4;

    constexpr int KpC = Kp / 4;
#pragma unroll
    for (int i = 0; i < (BM * KpC) / 256; i++) {
        int task = tid + i * 256;
        int row = task / KpC;
        int qg = (task % KpC) * 4;
        int gr = bm + row;
        if (gr >= M) gr = M - 1;
        cpasync16(smB + (uint32_t)(row * S + qg) * 4u, &Ah[(size_t)gr * Kp + qg]);
    }
#pragma unroll
    for (int i = 0; i < (BNT * KpC) / 256; i++) {
        int task = tid + i * 256;
        int n = task / KpC;
        int qg = (task % KpC) * 4;
        cpasync16(sBhB + (uint32_t)(n * S + qg) * 4u,
                  &g_wh[(size_t)wOff + (size_t)n * Kp + qg]);
    }
    cp_commit();
    cp_wait<0>();
    __syncthreads();

#pragma unroll
    for (int ks = 0; ks < KS; ks++) {
        uint32_t ah[2][4];
#pragma unroll
        for (int mt = 0; mt < 2; mt++) {
            uint32_t woff = (uint32_t)((wm * 32 + mt * 16 + aRow) * S + ks * 8 + aKh) * 4u;
            ldsm4(ah[mt], smB + woff);
        }
        uint32_t bh[NT][2];
#pragma unroll
        for (int j = 0; j < NT / 2; j++) {
            uint32_t woff = (uint32_t)((wn * (BNT / 2) + j * 16 + bN) * S + ks * 8 + bKh) * 4u;
            uint32_t rh[4];
            ldsm4(rh, sBhB + woff);
            bh[2 * j][0] = rh[0]; bh[2 * j][1] = rh[1];
            bh[2 * j + 1][0] = rh[2]; bh[2 * j + 1][1] = rh[3];
        }
#pragma unroll
        for (int mt = 0; mt < 2; mt++)
#pragma unroll
            for (int nt = 0; nt < NT; nt++)
                mma16816(c[mt][nt], ah[mt], bh[nt]);
    }
    __syncthreads();

    const int N = BNT;
    float* smemF = (float*)smem;
#pragma unroll
    for (int mt = 0; mt < 2; mt++)
#pragma unroll
        for (int nt = 0; nt < NT; nt++) {
            int r0 = wm * 32 + mt * 16 + gid;
            int gr0 = bm + r0;
            int gc = wn * (BNT / 2) + nt * 8 + tig * 2;
            float v0 = c[mt][nt][0], v1 = c[mt][nt][1];
            float v2 = c[mt][nt][2], v3 = c[mt][nt][3];
            if (FUSE) {
                float b0 = bias[gc], b1 = bias[gc + 1];
                v0 = fmaxf(v0 + b0, 0.f);
                v1 = fmaxf(v1 + b1, 0.f);
                v2 = fmaxf(v2 + b0, 0.f);
                v3 = fmaxf(v3 + b1, 0.f);
            }
            if (OMODE == 2) {
                if (gr0 < M)
                    OutH[(size_t)gr0 * (N >> 1) + (gc >> 1)] = cvt2(v0, v1);
                if (gr0 + 8 < M)
                    OutH[(size_t)(gr0 + 8) * (N >> 1) + (gc >> 1)] = cvt2(v2, v3);
            } else {
                smemF[r0 * 65 + gc] = v0;
                smemF[r0 * 65 + gc + 1] = v1;
                smemF[(r0 + 8) * 65 + gc] = v2;
                smemF[(r0 + 8) * 65 + gc + 1] = v3;
            }
        }

    if (OMODE == 3) {
        __syncthreads();
        if (tid < BM) {
            int g = bm + tid;
            if (g < M) {
                float a0 = bc3[0], a1 = bc3[1];
                const float* zr = &smemF[tid * 65];
#pragma unroll
                for (int k = 0; k < HF2; k++) {
                    float zv = zr[k];
                    a0 += zv * Wc3[2 * k + 0];
                    a1 += zv * Wc3[2 * k + 1];
                }
                float m = fmaxf(a0, a1);
                float l = logf(expf(a0 - m) + expf(a1 - m));
                Cf[2 * g + 0] = a0 - m - l;
                Cf[2 * g + 1] = a1 - m - l;
            }
        }
    }
}

// ---------------- bf16 gather aggregation ------------------------------------
// out[i] = relu(b + di*(di*h[i] + sum_e dinv_src*h[src]));  edge.y = dinv_src
// gather loads use .cg (zero reuse; skip L1 allocation)
template <int F>
__global__ void k_agg(const uint32_t* __restrict__ h, const float* __restrict__ bias,
                      uint32_t* __restrict__ outH) {
    int warp = (blockIdx.x * blockDim.x + threadIdx.x) >> 5;
    int lane = threadIdx.x & 31;
    if (warp >= NN) return;
    const int FP = F / 2;
    const int VPL = F / 32;
    float di = g_dinv[warp];
    float acc[VPL];

    auto loadrow = [&](int row, float2& a, float2& b) {
        if (VPL == 4) {
            uint2 v = __ldcg((const uint2*)(h + (size_t)row * FP + lane * 2));
            a = __bfloat1622float2(reinterpret_cast<__nv_bfloat162&>(v.x));
            b = __bfloat1622float2(reinterpret_cast<__nv_bfloat162&>(v.y));
        } else {
            uint32_t v = __ldcg((const unsigned int*)(h + (size_t)row * FP + lane));
            a = __bfloat1622float2(reinterpret_cast<__nv_bfloat162&>(v));
        }
    };

    {
        float2 a, b;
        loadrow(warp, a, b);
        acc[0] = a.x * di;
        acc[1] = a.y * di;
        if (VPL == 4) { acc[2] = b.x * di; acc[3] = b.y * di; }
    }

    int beg = g_rowptr[warp];
    int end = g_rowptr[warp + 1];
    int j = beg;
    for (; j + 3 < end; j += 4) {
        int2 e0 = g_edge[j];
        int2 e1 = g_edge[j + 1];
        int2 e2 = g_edge[j + 2];
        int2 e3 = g_edge[j + 3];
        float w0 = __int_as_float(e0.y);
        float w1 = __int_as_float(e1.y);
        float w2 = __int_as_float(e2.y);
        float w3 = __int_as_float(e3.y);
        float2 a0, b0, a1, b1, a2, b2, a3, b3;
        loadrow(e0.x, a0, b0);
        loadrow(e1.x, a1, b1);
        loadrow(e2.x, a2, b2);
        loadrow(e3.x, a3, b3);
        acc[0] += a0.x * w0; acc[1] += a0.y * w0;
        acc[0] += a1.x * w1; acc[1] += a1.y * w1;
        acc[0] += a2.x * w2; acc[1] += a2.y * w2;
        acc[0] += a3.x * w3; acc[1] += a3.y * w3;
        if (VPL == 4) {
            acc[2] += b0.x * w0; acc[3] += b0.y * w0;
            acc[2] += b1.x * w1; acc[3] += b1.y * w1;
            acc[2] += b2.x * w2; acc[3] += b2.y * w2;
            acc[2] += b3.x * w3; acc[3] += b3.y * w3;
        }
    }
    for (; j < end; j++) {
        int2 e0 = g_edge[j];
        float w0 = __int_as_float(e0.y);
        float2 a0, b0;
        loadrow(e0.x, a0, b0);
        acc[0] += a0.x * w0; acc[1] += a0.y * w0;
        if (VPL == 4) { acc[2] += b0.x * w0; acc[3] += b0.y * w0; }
    }

    if (VPL == 4) {
        float4 b = *(const float4*)&bias[lane * 4];
        float o0 = fmaxf(acc[0] * di + b.x, 0.f);
        float o1 = fmaxf(acc[1] * di + b.y, 0.f);
        float o2 = fmaxf(acc[2] * di + b.z, 0.f);
        float o3 = fmaxf(acc[3] * di + b.w, 0.f);
        size_t p = (size_t)warp * FP + lane * 2;
        *(uint2*)&outH[p] = make_uint2(cvt2(o0, o1), cvt2(o2, o3));
    } else {
        float2 b = *(const float2*)&bias[lane * 2];
        float o0 = fmaxf(acc[0] * di + b.x, 0.f);
        float o1 = fmaxf(acc[1] * di + b.y, 0.f);
        outH[(size_t)warp * FP + lane] = cvt2(o0, o1);
    }
}

// ---------------- launch -----------------------------------------------------
extern "C" void kernel_launch(void* const* d_in, const int* in_sizes, int n_in,
                              void* d_out, int out_size) {
    const float* x   = (const float*)d_in[0];
    const int*   ei  = (const int*)d_in[1];
    const float* W1  = (const float*)d_in[2];
    const float* b1  = (const float*)d_in[3];
    const float* W2  = (const float*)d_in[4];
    const float* b2  = (const float*)d_in[5];
    const float* W3  = (const float*)d_in[6];
    const float* b3  = (const float*)d_in[7];
    const float* Wc1 = (const float*)d_in[8];
    const float* bc1 = (const float*)d_in[9];
    const float* Wc2 = (const float*)d_in[10];
    const float* bc2 = (const float*)d_in[11];
    const float* Wc3 = (const float*)d_in[12];
    const float* bc3 = (const float*)d_in[13];
    float* out = (float*)d_out;

    uint32_t* bufH;
    uint32_t* aH;
    void* degPtr;
    cudaGetSymbolAddress((void**)&bufH, g_bufH);
    cudaGetSymbolAddress((void**)&aH, g_aH);
    cudaGetSymbolAddress(&degPtr, g_deg);

    const int SM_L128 = (128 + 128) * 68 * 4;   // 69632 (K=128, BNT=128)
    const int SM_L64  = (128 + 64) * 68 * 4;    // 52224 (K=128, BNT=64)
    const int SM_C1   = (128 + 128) * 100 * 4;  // 102400 (K=192, BNT=128)
    static bool attrDone = false;
    if (!attrDone) {
        cudaFuncSetAttribute(k_mma<128, 128, 2, false>, cudaFuncAttributeMaxDynamicSharedMemorySize, SM_L128);
        cudaFuncSetAttribute(k_mma<128, 64, 2, false>,  cudaFuncAttributeMaxDynamicSharedMemorySize, SM_L64);
        cudaFuncSetAttribute(k_mma<192, 128, 2, true>,  cudaFuncAttributeMaxDynamicSharedMemorySize, SM_C1);
        cudaFuncSetAttribute(k_mma<128, 64, 3, true>,   cudaFuncAttributeMaxDynamicSharedMemorySize, SM_L64);
        attrDone = true;
    }

    static cudaStream_t sB = nullptr;
    static cudaEvent_t evFork = nullptr, evJoin = nullptr;
    if (sB == nullptr) {
        cudaStreamCreateWithFlags(&sB, cudaStreamNonBlocking);
        cudaEventCreateWithFlags(&evFork, cudaEventDisableTiming);
        cudaEventCreateWithFlags(&evJoin, cudaEventDisableTiming);
    }

    const int aggBlocks = (NN * 32 + 255) / 256;
    dim3 gN(1, (NN + BM - 1) / BM);
    dim3 gC(1, (BBG + BM - 1) / BM);

    // --- fork: stream B does convert path + layer-1 GEMM ---
    cudaEventRecord(evFork, 0);
    cudaStreamWaitEvent(sB, evFork, 0);
    k_split<<<(XT + WPAIRS + 255) / 256, 256, 0, sB>>>(x, W1, W2, W3, Wc1, Wc2);
    k_mma<128, 128, 2, false><<<gN, 256, SM_L128, sB>>>(aH, WOFF1, nullptr, nullptr, bufH, NN, nullptr, nullptr);
    cudaEventRecord(evJoin, sB);

    // --- default stream: CSR build ---
    cudaMemsetAsync(degPtr, 0, NN * sizeof(int), 0);
    k_count<<<(EE / 4 + 255) / 256, 256>>>(ei);
    k_scan1<<<SCB, 1024>>>();
    k_scan2<<<1, 256>>>();
    k_scan3<<<SCB, 1024>>>();
    k_scatter<<<(EE / 2 + 255) / 256, 256>>>(ei);

    // --- join ---
    cudaStreamWaitEvent(0, evJoin, 0);

    // layer 1 agg
    k_agg<HF><<<aggBlocks, 256>>>(bufH, b1, aH);
    // layer 2
    k_mma<128, 128, 2, false><<<gN, 256, SM_L128>>>(aH, WOFF2, nullptr, nullptr, bufH, NN, nullptr, nullptr);
    k_agg<HF><<<aggBlocks, 256>>>(bufH, b2, aH);
    // layer 3 (128 -> 64)
    k_mma<128, 64, 2, false><<<gN, 256, SM_L64>>>(aH, WOFF3, nullptr, nullptr, bufH, NN, nullptr, nullptr);
    k_agg<HF2><<<aggBlocks, 256>>>(bufH, b3, aH);
    // classifier: input viewed as [50000, 192] (96 pairs/row)
    k_mma<192, 128, 2, true><<<gC, 256, SM_C1>>>(aH, WOFFC1, bc1, nullptr, aH + COFF, BBG, nullptr, nullptr);
    // gc2 + fused 64->2 + log_softmax
    k_mma<128, 64, 3, true><<<gC, 256, SM_L64>>>(aH + COFF, WOFFC2, bc2, out, nullptr, BBG, Wc3, bc3);
}

// round 17
// speedup vs baseline: 1.0440x; 1.0440x over previous
#include <cuda_runtime.h>
#include <cuda_bf16.h>
#include <stdint.h>
#include <math.h>

#define NN 150000
#define EE 2400000
#define BBG 50000
#define HF 128
#define HF2 64

#define WOFF1  0
#define WOFF2  8192
#define WOFF3  16384
#define WOFFC1 20480
#define WOFFC2 32768
#define WPAIRS 36864

#define COFF   4800000   // classifier intermediate offset in aH (words)
#define XT     4800000   // x-split tasks (NN*HF/4)
#define SCB    147       // scan blocks: ceil(150000/1024)

// ---------------- scratch (static device globals; no allocation) -------------
__device__ uint32_t g_bufH[(size_t)NN * HF / 2];      // bf162 GEMM outputs (agg input)
__device__ uint32_t g_aH[(size_t)NN * HF / 2];        // bf162 activations (GEMM input)
__device__ uint32_t g_wh[WPAIRS];                     // bf162 weights, n-major [n][k/2]
__device__ float g_dinv[NN];
__device__ int2  g_edge[EE];                          // {src, dinv[src]-as-int}
__device__ int   g_deg[NN];
__device__ int   g_rowptr[NN + 1];
__device__ int   g_cursor[NN];
__device__ int   g_part[256];

// ---------------- helpers ----------------------------------------------------
__device__ __forceinline__ uint32_t cvt2(float x, float y) {
    __nv_bfloat162 h = __floats2bfloat162_rn(x, y);
    return reinterpret_cast<uint32_t&>(h);
}

__device__ __forceinline__ void mma16816(float c[4], const uint32_t a[4], const uint32_t b[2]) {
    asm volatile(
        "mma.sync.aligned.m16n8k16.row.col.f32.bf16.bf16.f32 "
        "{%0,%1,%2,%3}, {%4,%5,%6,%7}, {%8,%9}, {%0,%1,%2,%3};"
        : "+f"(c[0]), "+f"(c[1]), "+f"(c[2]), "+f"(c[3])
        : "r"(a[0]), "r"(a[1]), "r"(a[2]), "r"(a[3]), "r"(b[0]), "r"(b[1]));
}

__device__ __forceinline__ void ldsm4(uint32_t r[4], uint32_t saddr) {
    asm volatile(
        "ldmatrix.sync.aligned.m8n8.x4.shared.b16 {%0,%1,%2,%3}, [%4];"
        : "=r"(r[0]), "=r"(r[1]), "=r"(r[2]), "=r"(r[3]) : "r"(saddr));
}

__device__ __forceinline__ void cpasync16(uint32_t smem, const void* gptr) {
    asm volatile("cp.async.cg.shared.global [%0], [%1], 16;" :: "r"(smem), "l"(gptr));
}
__device__ __forceinline__ void cp_commit() {
    asm volatile("cp.async.commit_group;");
}
template <int Nw>
__device__ __forceinline__ void cp_wait() {
    asm volatile("cp.async.wait_group %0;" :: "n"(Nw));
}

// ---------------- setup kernels ---------------------------------------------
// 2 edges per thread, vectorized dst load
__global__ void k_count(const int* __restrict__ ei) {
    int t = blockIdx.x * blockDim.x + threadIdx.x;
    if (t < EE / 2) {
        int2 d = ((const int2*)(ei + EE))[t];
        atomicAdd(&g_deg[d.x], 1);
        atomicAdd(&g_deg[d.y], 1);
    }
}

__global__ void k_scan1() {
    __shared__ int s[1024];
    int t = threadIdx.x;
    int i = blockIdx.x * 1024 + t;
    s[t] = (i < NN) ? g_deg[i] : 0;
    __syncthreads();
    for (int off = 512; off; off >>= 1) {
        if (t < off) s[t] += s[t + off];
        __syncthreads();
    }
    if (t == 0) g_part[blockIdx.x] = s[0];
}

__global__ void k_scan2() {
    __shared__ int s[256];
    int t = threadIdx.x;
    int v = (t < SCB) ? g_part[t] : 0;
    s[t] = v;
    __syncthreads();
    for (int off = 1; off < 256; off <<= 1) {
        int u = (t >= off) ? s[t - off] : 0;
        __syncthreads();
        s[t] += u;
        __syncthreads();
    }
    if (t < SCB) g_part[t] = s[t] - v;
    if (t == 255) g_rowptr[NN] = s[255];
}

__global__ void k_scan3() {
    __shared__ int s[1024];
    int t = threadIdx.x;
    int i = blockIdx.x * 1024 + t;
    int d = (i < NN) ? g_deg[i] : 0;
    s[t] = d;
    __syncthreads();
    for (int off = 1; off < 1024; off <<= 1) {
        int u = (t >= off) ? s[t - off] : 0;
        __syncthreads();
        s[t] += u;
        __syncthreads();
    }
    if (i < NN) {
        int excl = s[t] - d + g_part[blockIdx.x];
        g_rowptr[i] = excl;
        g_cursor[i] = excl;
        g_dinv[i] = rsqrtf((float)(d + 1));
    }
}

// 2 edges per thread; store (src, dinv[src]) into dense CSR
__global__ void k_scatter(const int* __restrict__ ei) {
    int t = blockIdx.x * blockDim.x + threadIdx.x;
    if (t < EE / 2) {
        int2 s = ((const int2*)ei)[t];
        int2 d = ((const int2*)(ei + EE))[t];
        int p0 = atomicAdd(&g_cursor[d.x], 1);
        g_edge[p0] = make_int2(s.x, __float_as_int(g_dinv[s.x]));
        int p1 = atomicAdd(&g_cursor[d.y], 1);
        g_edge[p1] = make_int2(s.y, __float_as_int(g_dinv[s.y]));
    }
}

// merged conversion: x chunks first, then weight pairs (n-major [n][k/2])
__global__ void k_split(const float* __restrict__ x,
                        const float* __restrict__ W1, const float* __restrict__ W2,
                        const float* __restrict__ W3, const float* __restrict__ Wc1,
                        const float* __restrict__ Wc2) {
    int i = blockIdx.x * blockDim.x + threadIdx.x;
    if (i < XT) {
        float4 v = ((const float4*)x)[i];
        ((uint2*)g_aH)[i] = make_uint2(cvt2(v.x, v.y), cvt2(v.z, v.w));
        return;
    }
    int p = i - XT;
    if (p >= WPAIRS) return;
    const float* src;
    int off, N, Kp;
    if (p < WOFF2)       { src = W1;  off = p - WOFF1;  N = 128; Kp = 64; }
    else if (p < WOFF3)  { src = W2;  off = p - WOFF2;  N = 128; Kp = 64; }
    else if (p < WOFFC1) { src = W3;  off = p - WOFF3;  N = 64;  Kp = 64; }
    else if (p < WOFFC2) { src = Wc1; off = p - WOFFC1; N = 128; Kp = 96; }
    else                 { src = Wc2; off = p - WOFFC2; N = 64;  Kp = 64; }
    int n = off / Kp, kp = off % Kp;
    g_wh[p] = cvt2(src[(size_t)(2 * kp) * N + n], src[(size_t)(2 * kp + 1) * N + n]);
}

// ---------------- bf16 MMA GEMM, single-shot K-panel load --------------------
// OMODE: 2 = bf162 out, 3 = fused 64->2 + log_softmax (final classifier)

#define BM 128

template <int KK, int BNT, int OMODE, bool FUSE>
__global__ void __launch_bounds__(256)
k_mma(const uint32_t* __restrict__ Ah, int wOff, const float* __restrict__ bias,
      float* __restrict__ Cf, uint32_t* __restrict__ OutH,
      int M,
      const float* __restrict__ Wc3, const float* __restrict__ bc3) {
    constexpr int NT = BNT / 16;
    constexpr int Kp = KK / 2;
    constexpr int S = Kp + 4;           // (Kp+4)%32==4 -> conflict-free; 16B-aligned
    constexpr int AW = BM * S;
    constexpr int KS = Kp / 8;

    extern __shared__ uint32_t smem[];

    const int tid = threadIdx.x;
    const int wid = tid >> 5;
    const int lane = tid & 31;
    const int wm = wid & 3;
    const int wn = wid >> 2;
    const int gid = lane >> 2;
    const int tig = lane & 3;
    const int bm = blockIdx.y * BM;

    const uint32_t smB = (uint32_t)__cvta_generic_to_shared(smem);
    const uint32_t sBhB = smB + AW * 4u;

    float c[2][NT][4];
#pragma unroll
    for (int mt = 0; mt < 2; mt++)
#pragma unroll
        for (int nt = 0; nt < NT; nt++)
#pragma unroll
            for (int j = 0; j < 4; j++) c[mt][nt][j] = 0.f;

    const int aRow = lane & 15;
    const int aKh = (lane >> 4) * 4;
    const int bN = (lane >> 4) * 8 + (lane & 7);
    const int bKh = ((lane >> 3) & 1) * 4;

    constexpr int KpC = Kp / 4;
#pragma unroll
    for (int i = 0; i < (BM * KpC) / 256; i++) {
        int task = tid + i * 256;
        int row = task / KpC;
        int qg = (task % KpC) * 4;
        int gr = bm + row;
        if (gr >= M) gr = M - 1;
        cpasync16(smB + (uint32_t)(row * S + qg) * 4u, &Ah[(size_t)gr * Kp + qg]);
    }
#pragma unroll
    for (int i = 0; i < (BNT * KpC) / 256; i++) {
        int task = tid + i * 256;
        int n = task / KpC;
        int qg = (task % KpC) * 4;
        cpasync16(sBhB + (uint32_t)(n * S + qg) * 4u,
                  &g_wh[(size_t)wOff + (size_t)n * Kp + qg]);
    }
    cp_commit();
    cp_wait<0>();
    __syncthreads();

#pragma unroll
    for (int ks = 0; ks < KS; ks++) {
        uint32_t ah[2][4];
#pragma unroll
        for (int mt = 0; mt < 2; mt++) {
            uint32_t woff = (uint32_t)((wm * 32 + mt * 16 + aRow) * S + ks * 8 + aKh) * 4u;
            ldsm4(ah[mt], smB + woff);
        }
        uint32_t bh[NT][2];
#pragma unroll
        for (int j = 0; j < NT / 2; j++) {
            uint32_t woff = (uint32_t)((wn * (BNT / 2) + j * 16 + bN) * S + ks * 8 + bKh) * 4u;
            uint32_t rh[4];
            ldsm4(rh, sBhB + woff);
            bh[2 * j][0] = rh[0]; bh[2 * j][1] = rh[1];
            bh[2 * j + 1][0] = rh[2]; bh[2 * j + 1][1] = rh[3];
        }
#pragma unroll
        for (int mt = 0; mt < 2; mt++)
#pragma unroll
            for (int nt = 0; nt < NT; nt++)
                mma16816(c[mt][nt], ah[mt], bh[nt]);
    }
    __syncthreads();

    const int N = BNT;
    float* smemF = (float*)smem;
#pragma unroll
    for (int mt = 0; mt < 2; mt++)
#pragma unroll
        for (int nt = 0; nt < NT; nt++) {
            int r0 = wm * 32 + mt * 16 + gid;
            int gr0 = bm + r0;
            int gc = wn * (BNT / 2) + nt * 8 + tig * 2;
            float v0 = c[mt][nt][0], v1 = c[mt][nt][1];
            float v2 = c[mt][nt][2], v3 = c[mt][nt][3];
            if (FUSE) {
                float b0 = bias[gc], b1 = bias[gc + 1];
                v0 = fmaxf(v0 + b0, 0.f);
                v1 = fmaxf(v1 + b1, 0.f);
                v2 = fmaxf(v2 + b0, 0.f);
                v3 = fmaxf(v3 + b1, 0.f);
            }
            if (OMODE == 2) {
                if (gr0 < M)
                    OutH[(size_t)gr0 * (N >> 1) + (gc >> 1)] = cvt2(v0, v1);
                if (gr0 + 8 < M)
                    OutH[(size_t)(gr0 + 8) * (N >> 1) + (gc >> 1)] = cvt2(v2, v3);
            } else {
                smemF[r0 * 65 + gc] = v0;
                smemF[r0 * 65 + gc + 1] = v1;
                smemF[(r0 + 8) * 65 + gc] = v2;
                smemF[(r0 + 8) * 65 + gc + 1] = v3;
            }
        }

    if (OMODE == 3) {
        __syncthreads();
        if (tid < BM) {
            int g = bm + tid;
            if (g < M) {
                float a0 = bc3[0], a1 = bc3[1];
                const float* zr = &smemF[tid * 65];
#pragma unroll
                for (int k = 0; k < HF2; k++) {
                    float zv = zr[k];
                    a0 += zv * Wc3[2 * k + 0];
                    a1 += zv * Wc3[2 * k + 1];
                }
                float m = fmaxf(a0, a1);
                float l = logf(expf(a0 - m) + expf(a1 - m));
                Cf[2 * g + 0] = a0 - m - l;
                Cf[2 * g + 1] = a1 - m - l;
            }
        }
    }
}

// ---------------- bf16 gather aggregation ------------------------------------
// out[i] = relu(b + di*(di*h[i] + sum_e dinv_src*h[src]));  edge.y = dinv_src
template <int F>
__global__ void k_agg(const uint32_t* __restrict__ h, const float* __restrict__ bias,
                      uint32_t* __restrict__ outH) {
    int warp = (blockIdx.x * blockDim.x + threadIdx.x) >> 5;
    int lane = threadIdx.x & 31;
    if (warp >= NN) return;
    const int FP = F / 2;
    const int VPL = F / 32;
    float di = g_dinv[warp];
    float acc[VPL];

    auto loadrow = [&](int row, float2& a, float2& b) {
        if (VPL == 4) {
            uint2 v = *(const uint2*)(h + (size_t)row * FP + lane * 2);
            a = __bfloat1622float2(reinterpret_cast<__nv_bfloat162&>(v.x));
            b = __bfloat1622float2(reinterpret_cast<__nv_bfloat162&>(v.y));
        } else {
            uint32_t v = h[(size_t)row * FP + lane];
            a = __bfloat1622float2(reinterpret_cast<__nv_bfloat162&>(v));
        }
    };

    {
        float2 a, b;
        loadrow(warp, a, b);
        acc[0] = a.x * di;
        acc[1] = a.y * di;
        if (VPL == 4) { acc[2] = b.x * di; acc[3] = b.y * di; }
    }

    int beg = g_rowptr[warp];
    int end = g_rowptr[warp + 1];
    int j = beg;
    for (; j + 3 < end; j += 4) {
        int2 e0 = g_edge[j];
        int2 e1 = g_edge[j + 1];
        int2 e2 = g_edge[j + 2];
        int2 e3 = g_edge[j + 3];
        float w0 = __int_as_float(e0.y);
        float w1 = __int_as_float(e1.y);
        float w2 = __int_as_float(e2.y);
        float w3 = __int_as_float(e3.y);
        float2 a0, b0, a1, b1, a2, b2, a3, b3;
        loadrow(e0.x, a0, b0);
        loadrow(e1.x, a1, b1);
        loadrow(e2.x, a2, b2);
        loadrow(e3.x, a3, b3);
        acc[0] += a0.x * w0; acc[1] += a0.y * w0;
        acc[0] += a1.x * w1; acc[1] += a1.y * w1;
        acc[0] += a2.x * w2; acc[1] += a2.y * w2;
        acc[0] += a3.x * w3; acc[1] += a3.y * w3;
        if (VPL == 4) {
            acc[2] += b0.x * w0; acc[3] += b0.y * w0;
            acc[2] += b1.x * w1; acc[3] += b1.y * w1;
            acc[2] += b2.x * w2; acc[3] += b2.y * w2;
            acc[2] += b3.x * w3; acc[3] += b3.y * w3;
        }
    }
    for (; j < end; j++) {
        int2 e0 = g_edge[j];
        float w0 = __int_as_float(e0.y);
        float2 a0, b0;
        loadrow(e0.x, a0, b0);
        acc[0] += a0.x * w0; acc[1] += a0.y * w0;
        if (VPL == 4) { acc[2] += b0.x * w0; acc[3] += b0.y * w0; }
    }

    if (VPL == 4) {
        float4 b = *(const float4*)&bias[lane * 4];
        float o0 = fmaxf(acc[0] * di + b.x, 0.f);
        float o1 = fmaxf(acc[1] * di + b.y, 0.f);
        float o2 = fmaxf(acc[2] * di + b.z, 0.f);
        float o3 = fmaxf(acc[3] * di + b.w, 0.f);
        size_t p = (size_t)warp * FP + lane * 2;
        *(uint2*)&outH[p] = make_uint2(cvt2(o0, o1), cvt2(o2, o3));
    } else {
        float2 b = *(const float2*)&bias[lane * 2];
        float o0 = fmaxf(acc[0] * di + b.x, 0.f);
        float o1 = fmaxf(acc[1] * di + b.y, 0.f);
        outH[(size_t)warp * FP + lane] = cvt2(o0, o1);
    }
}

// ---------------- launch -----------------------------------------------------
extern "C" void kernel_launch(void* const* d_in, const int* in_sizes, int n_in,
                              void* d_out, int out_size) {
    const float* x   = (const float*)d_in[0];
    const int*   ei  = (const int*)d_in[1];
    const float* W1  = (const float*)d_in[2];
    const float* b1  = (const float*)d_in[3];
    const float* W2  = (const float*)d_in[4];
    const float* b2  = (const float*)d_in[5];
    const float* W3  = (const float*)d_in[6];
    const float* b3  = (const float*)d_in[7];
    const float* Wc1 = (const float*)d_in[8];
    const float* bc1 = (const float*)d_in[9];
    const float* Wc2 = (const float*)d_in[10];
    const float* bc2 = (const float*)d_in[11];
    const float* Wc3 = (const float*)d_in[12];
    const float* bc3 = (const float*)d_in[13];
    float* out = (float*)d_out;

    uint32_t* bufH;
    uint32_t* aH;
    void* degPtr;
    cudaGetSymbolAddress((void**)&bufH, g_bufH);
    cudaGetSymbolAddress((void**)&aH, g_aH);
    cudaGetSymbolAddress(&degPtr, g_deg);

    const int SM_L128 = (128 + 128) * 68 * 4;   // 69632 (K=128, BNT=128)
    const int SM_L64  = (128 + 64) * 68 * 4;    // 52224 (K=128, BNT=64)
    const int SM_C1   = (128 + 128) * 100 * 4;  // 102400 (K=192, BNT=128)
    static bool attrDone = false;
    if (!attrDone) {
        cudaFuncSetAttribute(k_mma<128, 128, 2, false>, cudaFuncAttributeMaxDynamicSharedMemorySize, SM_L128);
        cudaFuncSetAttribute(k_mma<128, 64, 2, false>,  cudaFuncAttributeMaxDynamicSharedMemorySize, SM_L64);
        cudaFuncSetAttribute(k_mma<192, 128, 2, true>,  cudaFuncAttributeMaxDynamicSharedMemorySize, SM_C1);
        cudaFuncSetAttribute(k_mma<128, 64, 3, true>,   cudaFuncAttributeMaxDynamicSharedMemorySize, SM_L64);
        attrDone = true;
    }

    static cudaStream_t sB = nullptr;
    static cudaEvent_t evFork = nullptr, evJoin = nullptr;
    if (sB == nullptr) {
        cudaStreamCreateWithFlags(&sB, cudaStreamNonBlocking);
        cudaEventCreateWithFlags(&evFork, cudaEventDisableTiming);
        cudaEventCreateWithFlags(&evJoin, cudaEventDisableTiming);
    }

    const int aggBlocks = (NN * 32 + 255) / 256;
    dim3 gN(1, (NN + BM - 1) / BM);
    dim3 gC(1, (BBG + BM - 1) / BM);

    // --- fork: stream B does convert path + layer-1 GEMM ---
    cudaEventRecord(evFork, 0);
    cudaStreamWaitEvent(sB, evFork, 0);
    k_split<<<(XT + WPAIRS + 255) / 256, 256, 0, sB>>>(x, W1, W2, W3, Wc1, Wc2);
    k_mma<128, 128, 2, false><<<gN, 256, SM_L128, sB>>>(aH, WOFF1, nullptr, nullptr, bufH, NN, nullptr, nullptr);
    cudaEventRecord(evJoin, sB);

    // --- default stream: CSR build ---
    cudaMemsetAsync(degPtr, 0, NN * sizeof(int), 0);
    k_count<<<(EE / 2 + 255) / 256, 256>>>(ei);
    k_scan1<<<SCB, 1024>>>();
    k_scan2<<<1, 256>>>();
    k_scan3<<<SCB, 1024>>>();
    k_scatter<<<(EE / 2 + 255) / 256, 256>>>(ei);

    // --- join ---
    cudaStreamWaitEvent(0, evJoin, 0);

    // layer 1 agg
    k_agg<HF><<<aggBlocks, 256>>>(bufH, b1, aH);
    // layer 2
    k_mma<128, 128, 2, false><<<gN, 256, SM_L128>>>(aH, WOFF2, nullptr, nullptr, bufH, NN, nullptr, nullptr);
    k_agg<HF><<<aggBlocks, 256>>>(bufH, b2, aH);
    // layer 3 (128 -> 64)
    k_mma<128, 64, 2, false><<<gN, 256, SM_L64>>>(aH, WOFF3, nullptr, nullptr, bufH, NN, nullptr, nullptr);
    k_agg<HF2><<<aggBlocks, 256>>>(bufH, b3, aH);
    // classifier: input viewed as [50000, 192] (96 pairs/row)
    k_mma<192, 128, 2, true><<<gC, 256, SM_C1>>>(aH, WOFFC1, bc1, nullptr, aH + COFF, BBG, nullptr, nullptr);
    // gc2 + fused 64->2 + log_softmax
    k_mma<128, 64, 3, true><<<gC, 256, SM_L64>>>(aH + COFF, WOFFC2, bc2, out, nullptr, BBG, Wc3, bc3);
}